// round 7
// baseline (speedup 1.0000x reference)
#include <cuda_runtime.h>
#include <math.h>

// ---------------- problem constants ----------------
#define Bz   64
#define Dz   512
#define Hz   8
#define DHz  64
#define NL   6
#define Cz   1024
#define LKV  1025
#define FFz  2048
#define Tz   16
#define SAz  1088
#define NCH  32
#define DEPTH 8
#define BDS  1032
#define EPSRN 1e-4f
#define ATT_SCALE 0.125f

// ---------------- scratch (__device__ globals) ----------------
__device__ float g_rel[LKV * Dz];
__device__ float g_cat[Bz * SAz];
__device__ float g_tok[Bz * Dz];
__device__ float g_x[Bz * Dz];
__device__ float g_quk[Bz * Dz];
__device__ float g_qur[Bz * Dz];
__device__ float g_qkw[Bz * Hz * Dz];
__device__ float g_rv [Bz * Hz * Dz];
__device__ float g_bd [Bz * Hz * BDS];
__device__ float g_pm[Bz * NCH * Hz];
__device__ float g_ps[Bz * NCH * Hz];
__device__ float g_pctx[(size_t)Bz * NCH * Hz * Dz];
__device__ float g_av[Bz * Dz];
__device__ float g_h[Bz * Dz];
__device__ float g_ff[Bz * FFz];
__device__ float g_part[4 * Bz * Dz];

// ---------------- helpers ----------------
__device__ __forceinline__ unsigned long long pk2(float2 v) {
    unsigned long long r;
    asm("mov.b64 %0, {%1,%2};" : "=l"(r) : "f"(v.x), "f"(v.y));
    return r;
}
__device__ __forceinline__ float2 up2(unsigned long long r) {
    float2 v;
    asm("mov.b64 {%0,%1}, %2;" : "=f"(v.x), "=f"(v.y) : "l"(r));
    return v;
}
__device__ __forceinline__ void fma2(float2& c, float2 a, float2 b) {
    unsigned long long uc = pk2(c), ua = pk2(a), ub = pk2(b);
    asm("fma.rn.f32x2 %0, %1, %2, %0;" : "+l"(uc) : "l"(ua), "l"(ub));
    c = up2(uc);
}
__device__ __forceinline__ float wred(float v) {
#pragma unroll
    for (int o = 16; o; o >>= 1) v += __shfl_xor_sync(0xffffffffu, v, o);
    return v;
}
__device__ __forceinline__ void cpasync16(void* smem, const void* gmem) {
    unsigned sm = (unsigned)__cvta_generic_to_shared(smem);
    asm volatile("cp.async.cg.shared.global [%0], [%1], 16;" :: "r"(sm), "l"(gmem));
}
#define CP_COMMIT() asm volatile("cp.async.commit_group;")

// =====================================================================
// Generic 64-row tiled GEMM:  C[b, j] = sum_k A[b,k] * W(j,k)
//   modes: 0 store, 1 bias+gelu, 3 dual C=v+e1[jg],C2=v+e2[jg],
//          4 scale C=v*e1[jg], 5 bias C=v+e1[jg], 6 residual C=v+e2[ci]
//   nw != null: A rows rmsnorm'd on the fly (Ktot==512, lda==512)
//   parts != null (requires nw): A rows are first MATERIALIZED as
//       x = parts0+parts1+parts2+parts3 + pb2 + phres, written to xout
//       (and A must == xout), then rmsnorm'd. Fuses prior-layer ff2-reduce.
//   gridDim.z == 2 && blockIdx.z == 1: use Az2/Wz2/Cz2/modez2 (fused pair)
// =====================================================================
__global__ __launch_bounds__(256) void k_mm(
    const float* __restrict__ A, int lda, int aXs, int aYs,
    const float* __restrict__ W, int ldw, int wYs, int wLayout,
    float* __restrict__ C, int ldc, int cYs,
    int Ktot, int Nmax, int mode,
    const float* __restrict__ e1, const float* __restrict__ e2,
    float* __restrict__ C2, const float* __restrict__ nw,
    const float* __restrict__ Az2, const float* __restrict__ Wz2,
    float* __restrict__ Cz2, int modez2,
    const float* __restrict__ parts, const float* __restrict__ pb2,
    const float* __restrict__ phres, float* __restrict__ xout)
{
    __shared__ __align__(16) float As[64][68];
    __shared__ __align__(16) float Ws[64][68];
    __shared__ float rstd_s[64];
    if (blockIdx.z == 1) { A = Az2; W = Wz2; C = Cz2; mode = modez2; e1 = nullptr; }
    int jt = blockIdx.x, by = blockIdx.y;
    const float* Ab = A + (size_t)jt * aXs + (size_t)by * aYs;
    const float* Wb = W + (size_t)by * wYs;
    float* Cb = C + (size_t)by * cYs;
    int tid = threadIdx.x;
    int tx = tid & 15, ty = tid >> 4;
    float2 acc[4][2];
#pragma unroll
    for (int i = 0; i < 4; i++) { acc[i][0] = make_float2(0.f, 0.f); acc[i][1] = make_float2(0.f, 0.f); }
    int lr = tid >> 2;            // 0..63
    int lc = (tid & 3) * 16;      // 0,16,32,48

    if (nw) { // fused rmsnorm pre-pass over full 512-col rows
        int row = tid >> 2, seg = tid & 3;
        float ssum = 0.f;
        if (parts) {
            // materialize x = sum parts + b2 + h, write to xout, accumulate ss
            const float4* p0 = (const float4*)(parts + (size_t)row * 512 + seg * 128);
            const float4* p1 = p0 + (Bz * Dz) / 4;
            const float4* p2 = p1 + (Bz * Dz) / 4;
            const float4* p3 = p2 + (Bz * Dz) / 4;
            const float4* pb = (const float4*)(pb2 + seg * 128);
            const float4* ph = (const float4*)(phres + (size_t)row * 512 + seg * 128);
            float4* px = (float4*)(xout + (size_t)row * 512 + seg * 128);
#pragma unroll
            for (int i = 0; i < 32; i++) {
                float4 v = p0[i], t1 = p1[i], t2 = p2[i], t3 = p3[i], bb = pb[i], hh = ph[i];
                v.x += t1.x + t2.x + t3.x + bb.x + hh.x;
                v.y += t1.y + t2.y + t3.y + bb.y + hh.y;
                v.z += t1.z + t2.z + t3.z + bb.z + hh.z;
                v.w += t1.w + t2.w + t3.w + bb.w + hh.w;
                px[i] = v;
                ssum += v.x * v.x + v.y * v.y + v.z * v.z + v.w * v.w;
            }
        } else {
            const float4* p = (const float4*)(Ab + (size_t)row * lda + seg * 128);
#pragma unroll
            for (int i = 0; i < 32; i++) {
                float4 vq = p[i];
                ssum += vq.x * vq.x + vq.y * vq.y + vq.z * vq.z + vq.w * vq.w;
            }
        }
        ssum += __shfl_xor_sync(0xffffffffu, ssum, 1);
        ssum += __shfl_xor_sync(0xffffffffu, ssum, 2);
        if (seg == 0) rstd_s[row] = rsqrtf(ssum * (1.f / 512.f) + EPSRN);
        __syncthreads();
    }

    for (int kc = 0; kc < Ktot; kc += 64) {
        { // A tile transpose: As[k][b]
            const float4* src = (const float4*)(Ab + (size_t)lr * lda + kc + lc);
            float rsc = nw ? rstd_s[lr] : 1.f;
#pragma unroll
            for (int q = 0; q < 4; q++) {
                float4 vv = src[q];
                if (nw) {
                    float4 nv4 = *(const float4*)(nw + kc + lc + q * 4);
                    vv.x *= rsc * nv4.x; vv.y *= rsc * nv4.y;
                    vv.z *= rsc * nv4.z; vv.w *= rsc * nv4.w;
                }
                As[lc + q * 4 + 0][lr] = vv.x; As[lc + q * 4 + 1][lr] = vv.y;
                As[lc + q * 4 + 2][lr] = vv.z; As[lc + q * 4 + 3][lr] = vv.w;
            }
        }
        if (wLayout == 0) { // W[j][k] -> transpose into Ws[k][j]
            int jr = jt * 64 + lr; if (jr >= Nmax) jr = Nmax - 1;
            const float4* src = (const float4*)(Wb + (size_t)jr * ldw + kc + lc);
#pragma unroll
            for (int q = 0; q < 4; q++) {
                float4 vv = src[q];
                Ws[lc + q * 4 + 0][lr] = vv.x; Ws[lc + q * 4 + 1][lr] = vv.y;
                Ws[lc + q * 4 + 2][lr] = vv.z; Ws[lc + q * 4 + 3][lr] = vv.w;
            }
        } else {            // W[k][j] -> direct copy Ws[k][j]
            const float4* src = (const float4*)(Wb + (size_t)(kc + lr) * ldw + jt * 64 + lc);
            float4* dst = (float4*)&Ws[lr][lc];
#pragma unroll
            for (int q = 0; q < 4; q++) dst[q] = src[q];
        }
        __syncthreads();
#pragma unroll 16
        for (int kk = 0; kk < 64; kk++) {
            float4 a4 = *(const float4*)&As[kk][ty * 4];
            float4 w4 = *(const float4*)&Ws[kk][tx * 4];
            float2 w01 = make_float2(w4.x, w4.y), w23 = make_float2(w4.z, w4.w);
            fma2(acc[0][0], make_float2(a4.x, a4.x), w01);
            fma2(acc[0][1], make_float2(a4.x, a4.x), w23);
            fma2(acc[1][0], make_float2(a4.y, a4.y), w01);
            fma2(acc[1][1], make_float2(a4.y, a4.y), w23);
            fma2(acc[2][0], make_float2(a4.z, a4.z), w01);
            fma2(acc[2][1], make_float2(a4.z, a4.z), w23);
            fma2(acc[3][0], make_float2(a4.w, a4.w), w01);
            fma2(acc[3][1], make_float2(a4.w, a4.w), w23);
        }
        __syncthreads();
    }
    int b0 = ty * 4, j0 = tx * 4;
#pragma unroll
    for (int i = 0; i < 4; i++) {
        float vals[4] = {acc[i][0].x, acc[i][0].y, acc[i][1].x, acc[i][1].y};
#pragma unroll
        for (int u = 0; u < 4; u++) {
            int jg = jt * 64 + j0 + u;
            if (jg >= Nmax) continue;
            size_t ci = (size_t)(b0 + i) * ldc + jg;
            float vv = vals[u];
            if (mode == 0)      Cb[ci] = vv;
            else if (mode == 1) { vv += e1[jg]; Cb[ci] = 0.5f * vv * (1.f + erff(vv * 0.70710678118654752f)); }
            else if (mode == 3) { Cb[ci] = vv + e1[jg]; C2[ci] = vv + e2[jg]; }
            else if (mode == 4) Cb[ci] = vv * e1[jg];
            else if (mode == 5) Cb[ci] = vv + e1[jg];
            else if (mode == 6) Cb[ci] = vv + e2[ci];
        }
    }
}

// ---------------- rel-pos table ----------------
__global__ void k_rel() {
    int k = blockIdx.x, j = threadIdx.x;
    float p = (float)(1024 - k);
    int jj = (j < 256) ? j : j - 256;
    float invf = expf(-(float)jj * (9.210340371976184f / 256.0f));
    float a = p * invf;
    g_rel[k * Dz + j] = (j < 256) ? sinf(a) : cosf(a);
}

// ---------------- cat(stoch, action_norm) ----------------
__global__ __launch_bounds__(256) void k_prep(const float* __restrict__ stoch,
                                              const float* __restrict__ action) {
    int b = blockIdx.x, tid = threadIdx.x;
    for (int i = tid; i < 1024; i += 256) g_cat[b * SAz + i] = stoch[b * 1024 + i];
    if (tid < 64) {
        float a = action[b * 64 + tid];
        g_cat[b * SAz + 1024 + tid] = a / fmaxf(fabsf(a), 1.0f);
    }
}

// ---------------- silu(rmsnorm(tok)) -> g_x ----------------
__global__ __launch_bounds__(256) void k_silu(const float* __restrict__ inw) {
    int b = blockIdx.x, tid = threadIdx.x, w = tid >> 5, lane = tid & 31;
    __shared__ float red[9];
    float2 xv = ((const float2*)(g_tok + b * Dz))[tid];
    float ss = fmaf(xv.x, xv.x, xv.y * xv.y);
    ss = wred(ss);
    if (lane == 0) red[w] = ss;
    __syncthreads();
    if (tid == 0) { float t = 0; for (int i = 0; i < 8; i++) t += red[i]; red[8] = rsqrtf(t / 512.f + EPSRN); }
    __syncthreads();
    float rstd = red[8];
    float2 nv = ((const float2*)inw)[tid];
    float yx = xv.x * rstd * nv.x, yy = xv.y * rstd * nv.y;
    float2 o = make_float2(yx / (1.f + __expf(-yx)), yy / (1.f + __expf(-yy)));
    ((float2*)(g_x + b * Dz))[tid] = o;
}

// ---------------- streaming attention v3: 128 thr, 2 heads/warp ----------------
__global__ __launch_bounds__(128) void k_att(int l,
                                             const float* __restrict__ cache,
                                             float* __restrict__ ncache_l) {
    int c = blockIdx.x, b = blockIdx.y;
    int tid = threadIdx.x, w = tid >> 5, lane = tid & 31;
    __shared__ __align__(16) float rowb[DEPTH][Dz]; // 16KB ring
    const float* cache_l = cache + (size_t)l * Bz * Cz * Dz;
    int start = c * 32;
    int cnt = (c == NCH - 1) ? 33 : 32;
    int h0 = 2 * w;

    const float2* qa = (const float2*)(g_qkw + ((size_t)b * Hz + h0) * Dz);
    float2 qA[8], qB[8];
#pragma unroll
    for (int i = 0; i < 8; i++) { qA[i] = qa[lane + 32 * i]; qB[i] = qa[256 + lane + 32 * i]; }
    const float* bdA = g_bd + ((size_t)b * Hz + h0) * BDS;
    float mA = -1e30f, sA = 0.f, mB = -1e30f, sB = 0.f;
    float2 cA[8], cB[8];
#pragma unroll
    for (int i = 0; i < 8; i++) { cA[i] = make_float2(0.f, 0.f); cB[i] = make_float2(0.f, 0.f); }

    // prologue: 7 rows in flight (each thread copies 16B of the 2KB row)
#pragma unroll
    for (int d = 0; d < 7; d++) {
        int k = start + d;
        if (d < cnt) {
            const float* src = (k < Cz) ? cache_l + ((size_t)b * Cz + k) * Dz
                                        : g_x + b * Dz;
            cpasync16(&rowb[d][tid * 4], src + tid * 4);
        }
        CP_COMMIT();
    }

    for (int r = 0; r < cnt; r++) {
        asm volatile("cp.async.wait_group 6;");
        __syncthreads();
        int kn = start + r + 7;
        if (r + 7 < cnt) {
            const float* src = (kn < Cz) ? cache_l + ((size_t)b * Cz + kn) * Dz
                                         : g_x + b * Dz;
            cpasync16(&rowb[(r + 7) & (DEPTH - 1)][tid * 4], src + tid * 4);
        }
        CP_COMMIT();
        int k = start + r;
        const float2* row2 = (const float2*)rowb[r & (DEPTH - 1)];
        float2 vA = make_float2(0.f, 0.f), vB = make_float2(0.f, 0.f), vS = make_float2(0.f, 0.f);
        float2 rr[8];
#pragma unroll
        for (int i = 0; i < 8; i++) {
            float2 rv = row2[lane + 32 * i];
            rr[i] = rv;
            fma2(vA, qA[i], rv);
            fma2(vB, qB[i], rv);
            fma2(vS, rv, rv);
        }
        float kA = vA.x + vA.y, kB = vB.x + vB.y, ssv = vS.x + vS.y;
#pragma unroll
        for (int o = 16; o; o >>= 1) {
            kA += __shfl_xor_sync(0xffffffffu, kA, o);
            kB += __shfl_xor_sync(0xffffffffu, kB, o);
            ssv += __shfl_xor_sync(0xffffffffu, ssv, o);
        }
        float rstd = rsqrtf(ssv * (1.f / 512.f) + EPSRN);
        float scA = ATT_SCALE * fmaf(rstd, kA, bdA[k]);
        float scB = ATT_SCALE * fmaf(rstd, kB, bdA[BDS + k]);
        // head A online softmax
        float mnA = fmaxf(mA, scA);
        float pA = __expf(scA - mnA);
        if (mnA > mA && mA > -1e29f) {
            float al = __expf(mA - mnA);
            sA *= al;
#pragma unroll
            for (int i = 0; i < 8; i++) { cA[i].x *= al; cA[i].y *= al; }
        }
        mA = mnA; sA += pA;
        // head B online softmax
        float mnB = fmaxf(mB, scB);
        float pB = __expf(scB - mnB);
        if (mnB > mB && mB > -1e29f) {
            float al = __expf(mB - mnB);
            sB *= al;
#pragma unroll
            for (int i = 0; i < 8; i++) { cB[i].x *= al; cB[i].y *= al; }
        }
        mB = mnB; sB += pB;
        float2 pA2 = make_float2(pA * rstd, pA * rstd);
        float2 pB2 = make_float2(pB * rstd, pB * rstd);
#pragma unroll
        for (int i = 0; i < 8; i++) { fma2(cA[i], pA2, rr[i]); fma2(cB[i], pB2, rr[i]); }
        // fused cache shift (row k -> new_cache row k-1); k==Cz writes x as last row
        if (k >= 1)
            __stcs(((float4*)(ncache_l + ((size_t)b * Cz + (k - 1)) * Dz)) + tid,
                   ((const float4*)row2)[tid]);
    }
    int pi = (b * NCH + c) * Hz + h0;
    if (lane == 0) { g_pm[pi] = mA; g_ps[pi] = sA; g_pm[pi + 1] = mB; g_ps[pi + 1] = sB; }
    float2* po = (float2*)(g_pctx + (size_t)pi * Dz);
#pragma unroll
    for (int i = 0; i < 8; i++) { po[lane + 32 * i] = cA[i]; po[256 + lane + 32 * i] = cB[i]; }
}

// ---------------- merge softmax partials + av GEMV (fused) ----------------
__global__ __launch_bounds__(256) void k_mav(int l, const float* __restrict__ n1w,
                                             const float* __restrict__ wv) {
    int b = blockIdx.x, h = blockIdx.y;
    int tid = threadIdx.x, w = tid >> 5, lane = tid & 31;
    __shared__ float wch[NCH];
    __shared__ float sinv;
    __shared__ __align__(16) float ctxs[Dz];
    if (tid < 32) {
        float mv = g_pm[(b * NCH + tid) * Hz + h];
        float M = mv;
#pragma unroll
        for (int o = 16; o; o >>= 1) M = fmaxf(M, __shfl_xor_sync(0xffffffffu, M, o));
        float e = __expf(mv - M);
        float sv = g_ps[(b * NCH + tid) * Hz + h] * e;
#pragma unroll
        for (int o = 16; o; o >>= 1) sv += __shfl_xor_sync(0xffffffffu, sv, o);
        wch[tid] = e;
        if (tid == 0) sinv = 1.f / sv;
    }
    __syncthreads();
    float2 acc = make_float2(0.f, 0.f);
#pragma unroll
    for (int ch = 0; ch < NCH; ch++) {
        float2 pv = ((const float2*)(g_pctx + (size_t)((b * NCH + ch) * Hz + h) * Dz))[tid];
        float2 w2 = make_float2(wch[ch], wch[ch]);
        fma2(acc, w2, pv);
    }
    float inv = sinv;
    float2 nv = ((const float2*)(n1w + l * Dz))[tid];
    acc.x *= inv * nv.x;
    acc.y *= inv * nv.y;
    ((float2*)ctxs)[tid] = acc;
    __syncthreads();
    const float* wvl = wv + ((size_t)l * Dz + (size_t)h * 64) * Dz;
    const float2* c2 = (const float2*)ctxs;
#pragma unroll
    for (int it = 0; it < 8; it++) {
        int j = w * 8 + it;
        const float2* wr2 = (const float2*)(wvl + (size_t)j * Dz);
        float2 a = make_float2(0.f, 0.f);
#pragma unroll
        for (int kq = 0; kq < 8; kq++) { int idx = lane + 32 * kq; fma2(a, c2[idx], wr2[idx]); }
        float rsum = wred(a.x + a.y);
        if (lane == 0) g_av[(size_t)b * Dz + h * 64 + j] = rsum;
    }
}

// ---------------- ff2 partial reduce + bias + residual -> new x (last layer only) ----------------
__global__ __launch_bounds__(256) void k_ff2red(const float* __restrict__ b2l) {
    int b = blockIdx.x, tid = threadIdx.x;
    float2 s = ((const float2*)(g_part + (size_t)b * Dz))[tid];
#pragma unroll
    for (int ks = 1; ks < 4; ks++) {
        float2 p = ((const float2*)(g_part + (size_t)ks * Bz * Dz + (size_t)b * Dz))[tid];
        s.x += p.x; s.y += p.y;
    }
    float2 bb = ((const float2*)b2l)[tid];
    float2 hh = ((const float2*)(g_h + (size_t)b * Dz))[tid];
    ((float2*)(g_x + (size_t)b * Dz))[tid] = make_float2(s.x + bb.x + hh.x, s.y + bb.y + hh.y);
}

// ---------------- final ----------------
__global__ __launch_bounds__(256) void k_final(const float* __restrict__ summary,
                                               const float* __restrict__ onw,
                                               float* __restrict__ out_deter,
                                               float* __restrict__ out_summ) {
    int t = blockIdx.x, b = blockIdx.y, tid = threadIdx.x, w = tid >> 5, lane = tid & 31;
    __shared__ float row[Dz];
    __shared__ float red[9];
    const float* src = (t < Tz - 1) ? (summary + ((size_t)b * Tz + t + 1) * Dz) : (g_x + b * Dz);
    float ss = 0.f;
    for (int i = tid; i < Dz; i += 256) { float vv = src[i]; row[i] = vv; ss = fmaf(vv, vv, ss); }
    ss = wred(ss);
    if (lane == 0) red[w] = ss;
    __syncthreads();
    if (tid == 0) { float tt = 0; for (int i = 0; i < 8; i++) tt += red[i]; red[8] = rsqrtf(tt / 512.f + EPSRN); }
    __syncthreads();
    float rstd = red[8];
    for (int i = tid; i < Dz; i += 256) {
        out_summ[((size_t)b * Tz + t) * Dz + i] = row[i];
        out_deter[(size_t)b * (Tz * Dz) + t * Dz + i] = row[i] * rstd * onw[i];
    }
}

// ---------------- launch ----------------
extern "C" void kernel_launch(void* const* d_in, const int* in_sizes, int n_in,
                              void* d_out, int out_size) {
    (void)in_sizes; (void)n_in; (void)out_size;
    const float* stoch      = (const float*)d_in[0];
    const float* action     = (const float*)d_in[1];
    const float* cache      = (const float*)d_in[2];
    const float* summary    = (const float*)d_in[3];
    const float* in_w       = (const float*)d_in[4];
    const float* in_b       = (const float*)d_in[5];
    const float* in_norm_w  = (const float*)d_in[6];
    const float* n1w        = (const float*)d_in[7];
    const float* wq         = (const float*)d_in[8];
    const float* wk         = (const float*)d_in[9];
    const float* wv         = (const float*)d_in[10];
    const float* wr         = (const float*)d_in[11];
    const float* wo         = (const float*)d_in[12];
    const float* u          = (const float*)d_in[13];
    const float* v          = (const float*)d_in[14];
    const float* n2w        = (const float*)d_in[15];
    const float* ff_w1      = (const float*)d_in[16];
    const float* ff_b1      = (const float*)d_in[17];
    const float* ff_w2      = (const float*)d_in[18];
    const float* ff_b2      = (const float*)d_in[19];
    const float* out_norm_w = (const float*)d_in[20];

    float* out = (float*)d_out;
    float* out_deter = out;
    float* out_cache = out + (size_t)Bz * Tz * Dz;
    float* out_summ  = out_cache + (size_t)NL * Bz * Cz * Dz;

    float *p_cat, *p_tok, *p_x, *p_quk, *p_qur, *p_qkw, *p_rv, *p_bd,
          *p_rel, *p_av, *p_h, *p_ff, *p_part;
    cudaGetSymbolAddress((void**)&p_cat,  g_cat);
    cudaGetSymbolAddress((void**)&p_tok,  g_tok);
    cudaGetSymbolAddress((void**)&p_x,    g_x);
    cudaGetSymbolAddress((void**)&p_quk,  g_quk);
    cudaGetSymbolAddress((void**)&p_qur,  g_qur);
    cudaGetSymbolAddress((void**)&p_qkw,  g_qkw);
    cudaGetSymbolAddress((void**)&p_rv,   g_rv);
    cudaGetSymbolAddress((void**)&p_bd,   g_bd);
    cudaGetSymbolAddress((void**)&p_rel,  g_rel);
    cudaGetSymbolAddress((void**)&p_av,   g_av);
    cudaGetSymbolAddress((void**)&p_h,    g_h);
    cudaGetSymbolAddress((void**)&p_ff,   g_ff);
    cudaGetSymbolAddress((void**)&p_part, g_part);

    k_prep<<<Bz, 256>>>(stoch, action);                                  // 1
    k_mm<<<8, 256>>>(p_cat, SAz, 0, 0, in_w, SAz, 0, 0, p_tok, Dz, 0,    // 2
                     SAz, Dz, 5, in_b, nullptr, nullptr, nullptr,
                     nullptr, nullptr, nullptr, 0,
                     nullptr, nullptr, nullptr, nullptr);
    k_silu<<<Bz, 256>>>(in_norm_w);                                      // 3
    // PROBE (4th launch -> ncu capture): full k_att on stale qkw/bd.
    // Its pctx/pm/ps outputs are overwritten by the real layer-0 k_att;
    // its ncache writes equal the real ones (pure input shift + g_x last row).
    k_att<<<dim3(NCH, Bz), 128>>>(0, cache, out_cache);                  // 4
    k_rel<<<LKV, 512>>>();                                               // 5

    for (int l = 0; l < NL; l++) {
        float* nc_l = out_cache + (size_t)l * Bz * Cz * Dz;
        const float* wql = wq + (size_t)l * Dz * Dz;
        const float* wkl = wk + (size_t)l * Dz * Dz;
        const float* wrl = wr + (size_t)l * Dz * Dz;
        const float* wol = wo + (size_t)l * Dz * Dz;

        // Q = rmsnorm(x)*n1 @ wq^T; for l>0 also materializes x from
        // prior layer's ff2 partials (fused ff2-reduce). Quk=Q+u, Qur=Q+v.
        k_mm<<<8, 256>>>(p_x, Dz, 0, 0, wql, Dz, 0, 0, p_quk, Dz, 0,
                         Dz, Dz, 3, u + l * Dz, v + l * Dz, p_qur, n1w + l * Dz,
                         nullptr, nullptr, nullptr, 0,
                         (l > 0) ? p_part : nullptr,
                         (l > 0) ? (ff_b2 + (size_t)(l - 1) * Dz) : nullptr,
                         p_h, p_x);
        // fused pair: z=0 qkw = Quk@wk_head * n1 ; z=1 rv = Qur@wr_head
        k_mm<<<dim3(8, 8, 2), 256>>>(p_quk, Dz, 0, 64, wkl, Dz, 64 * Dz, 1,
                                     p_qkw, Hz * Dz, Dz, 64, Dz, 4,
                                     n1w + l * Dz, nullptr, nullptr, nullptr,
                                     p_qur, wrl, p_rv, 0,
                                     nullptr, nullptr, nullptr, nullptr);
        // bd(512x1025) = rv @ rel^T
        k_mm<<<dim3(17, 8), 256>>>(p_rv, Dz, 0, 64 * Dz, p_rel, Dz, 0, 0,
                                   p_bd, BDS, 64 * BDS, Dz, LKV, 0,
                                   nullptr, nullptr, nullptr, nullptr,
                                   nullptr, nullptr, nullptr, 0,
                                   nullptr, nullptr, nullptr, nullptr);
        k_att<<<dim3(NCH, Bz), 128>>>(l, cache, nc_l);
        k_mav<<<dim3(Bz, Hz), 256>>>(l, n1w, wv);
        // h = x + av @ wo^T
        k_mm<<<8, 256>>>(p_av, Dz, 0, 0, wol, Dz, 0, 0, p_h, Dz, 0,
                         Dz, Dz, 6, nullptr, p_x, nullptr, nullptr,
                         nullptr, nullptr, nullptr, 0,
                         nullptr, nullptr, nullptr, nullptr);
        // ff hidden = gelu(rmsnorm(h)*n2 @ w1^T + b1)
        k_mm<<<32, 256>>>(p_h, Dz, 0, 0, ff_w1 + (size_t)l * FFz * Dz, Dz, 0, 0,
                          p_ff, FFz, 0, Dz, FFz, 1,
                          ff_b1 + (size_t)l * FFz, nullptr, nullptr, n2w + l * Dz,
                          nullptr, nullptr, nullptr, 0,
                          nullptr, nullptr, nullptr, nullptr);
        // ff2 split-K partials (reduced by next layer's Q k_mm, or k_ff2red at end)
        k_mm<<<dim3(8, 4), 256>>>(p_ff, FFz, 0, 512, ff_w2 + (size_t)l * Dz * FFz, FFz, 512, 0,
                                  p_part, Dz, Bz * Dz, 512, Dz, 0,
                                  nullptr, nullptr, nullptr, nullptr,
                                  nullptr, nullptr, nullptr, 0,
                                  nullptr, nullptr, nullptr, nullptr);
    }
    k_ff2red<<<Bz, 256>>>(ff_b2 + (size_t)(NL - 1) * Dz);
    k_final<<<dim3(Tz, Bz), 256>>>(summary, out_norm_w, out_deter, out_summ);
}

// round 9
// speedup vs baseline: 1.1198x; 1.1198x over previous
#include <cuda_runtime.h>
#include <math.h>

// ---------------- problem constants ----------------
#define Bz   64
#define Dz   512
#define Hz   8
#define DHz  64
#define NL   6
#define Cz   1024
#define LKV  1025
#define FFz  2048
#define Tz   16
#define SAz  1088
#define NCH  32
#define DEPTH 4
#define BDS  1032
#define EPSRN 1e-4f
#define ATT_SCALE 0.125f

// ---------------- scratch (__device__ globals) ----------------
__device__ float g_rel[LKV * Dz];
__device__ float g_cat[Bz * SAz];
__device__ float g_tok[Bz * Dz];
__device__ float g_x[Bz * Dz];
__device__ float g_quk[Bz * Dz];
__device__ float g_qur[Bz * Dz];
__device__ float g_qkw[Bz * Hz * Dz];
__device__ float g_rv [Bz * Hz * Dz];
__device__ float g_bd [Bz * Hz * BDS];
__device__ float g_pm[Bz * NCH * Hz];
__device__ float g_ps[Bz * NCH * Hz];
__device__ float g_pctx[(size_t)Bz * NCH * Hz * Dz];
__device__ float g_av[Bz * Dz];
__device__ float g_h[Bz * Dz];
__device__ float g_ff[Bz * FFz];
__device__ float g_part[4 * Bz * Dz];

// ---------------- helpers ----------------
__device__ __forceinline__ unsigned long long pk2(float2 v) {
    unsigned long long r;
    asm("mov.b64 %0, {%1,%2};" : "=l"(r) : "f"(v.x), "f"(v.y));
    return r;
}
__device__ __forceinline__ float2 up2(unsigned long long r) {
    float2 v;
    asm("mov.b64 {%0,%1}, %2;" : "=f"(v.x), "=f"(v.y) : "l"(r));
    return v;
}
__device__ __forceinline__ void fma2(float2& c, float2 a, float2 b) {
    unsigned long long uc = pk2(c), ua = pk2(a), ub = pk2(b);
    asm("fma.rn.f32x2 %0, %1, %2, %0;" : "+l"(uc) : "l"(ua), "l"(ub));
    c = up2(uc);
}
__device__ __forceinline__ float wred(float v) {
#pragma unroll
    for (int o = 16; o; o >>= 1) v += __shfl_xor_sync(0xffffffffu, v, o);
    return v;
}
__device__ __forceinline__ void cpasync16(void* smem, const void* gmem) {
    unsigned sm = (unsigned)__cvta_generic_to_shared(smem);
    asm volatile("cp.async.cg.shared.global [%0], [%1], 16;" :: "r"(sm), "l"(gmem));
}
#define CP_COMMIT() asm volatile("cp.async.commit_group;")

// =====================================================================
// Generic 64-row tiled GEMM with register-staged double buffering.
//   C[b, j] = sum_k A[b,k] * W(j,k)
//   modes: 0 store, 1 bias+gelu, 3 dual C=v+e1[jg],C2=v+e2[jg],
//          4 scale C=v*e1[jg], 5 bias C=v+e1[jg], 6 residual C=v+e2[ci]
//   nw != null: A rows rmsnorm'd on the fly (Ktot==512, lda==512)
//   parts != null (requires nw): materialize x = sum(parts)+pb2+phres -> xout
//   gridDim.z == 2 && blockIdx.z == 1: use Az2/Wz2/Cz2/modez2 (fused pair)
// =====================================================================
__global__ __launch_bounds__(256) void k_mm(
    const float* __restrict__ A, int lda, int aXs, int aYs,
    const float* __restrict__ W, int ldw, int wYs, int wLayout,
    float* __restrict__ C, int ldc, int cYs,
    int Ktot, int Nmax, int mode,
    const float* __restrict__ e1, const float* __restrict__ e2,
    float* __restrict__ C2, const float* __restrict__ nw,
    const float* __restrict__ Az2, const float* __restrict__ Wz2,
    float* __restrict__ Cz2, int modez2,
    const float* __restrict__ parts, const float* __restrict__ pb2,
    const float* __restrict__ phres, float* __restrict__ xout)
{
    __shared__ __align__(16) float As[64][68];
    __shared__ __align__(16) float Ws[64][68];
    __shared__ float rstd_s[64];
    if (blockIdx.z == 1) { A = Az2; W = Wz2; C = Cz2; mode = modez2; e1 = nullptr; }
    int jt = blockIdx.x, by = blockIdx.y;
    const float* Ab = A + (size_t)jt * aXs + (size_t)by * aYs;
    const float* Wb = W + (size_t)by * wYs;
    float* Cb = C + (size_t)by * cYs;
    int tid = threadIdx.x;
    int tx = tid & 15, ty = tid >> 4;
    float2 acc[4][2];
#pragma unroll
    for (int i = 0; i < 4; i++) { acc[i][0] = make_float2(0.f, 0.f); acc[i][1] = make_float2(0.f, 0.f); }
    int lr = tid >> 2;            // 0..63
    int lc = (tid & 3) * 16;      // 0,16,32,48
    int jrW = jt * 64 + lr; if (jrW >= Nmax) jrW = Nmax - 1;

    if (nw) { // fused rmsnorm pre-pass over full 512-col rows
        int row = tid >> 2, seg = tid & 3;
        float ssum = 0.f;
        if (parts) {
            const float4* p0 = (const float4*)(parts + (size_t)row * 512 + seg * 128);
            const float4* p1 = p0 + (Bz * Dz) / 4;
            const float4* p2 = p1 + (Bz * Dz) / 4;
            const float4* p3 = p2 + (Bz * Dz) / 4;
            const float4* pb = (const float4*)(pb2 + seg * 128);
            const float4* ph = (const float4*)(phres + (size_t)row * 512 + seg * 128);
            float4* px = (float4*)(xout + (size_t)row * 512 + seg * 128);
#pragma unroll
            for (int i = 0; i < 32; i++) {
                float4 v = p0[i], t1 = p1[i], t2 = p2[i], t3 = p3[i], bb = pb[i], hh = ph[i];
                v.x += t1.x + t2.x + t3.x + bb.x + hh.x;
                v.y += t1.y + t2.y + t3.y + bb.y + hh.y;
                v.z += t1.z + t2.z + t3.z + bb.z + hh.z;
                v.w += t1.w + t2.w + t3.w + bb.w + hh.w;
                px[i] = v;
                ssum += v.x * v.x + v.y * v.y + v.z * v.z + v.w * v.w;
            }
        } else {
            const float4* p = (const float4*)(Ab + (size_t)row * lda + seg * 128);
#pragma unroll
            for (int i = 0; i < 32; i++) {
                float4 vq = p[i];
                ssum += vq.x * vq.x + vq.y * vq.y + vq.z * vq.z + vq.w * vq.w;
            }
        }
        ssum += __shfl_xor_sync(0xffffffffu, ssum, 1);
        ssum += __shfl_xor_sync(0xffffffffu, ssum, 2);
        if (seg == 0) rstd_s[row] = rsqrtf(ssum * (1.f / 512.f) + EPSRN);
        __syncthreads();
    }

    // register staging for double buffering
    float4 aS[4], wS[4];
    {
        const float4* srcA = (const float4*)(Ab + (size_t)lr * lda + lc);
#pragma unroll
        for (int q = 0; q < 4; q++) aS[q] = srcA[q];
        const float4* srcW = (wLayout == 0)
            ? (const float4*)(Wb + (size_t)jrW * ldw + lc)
            : (const float4*)(Wb + (size_t)lr * ldw + jt * 64 + lc);
#pragma unroll
        for (int q = 0; q < 4; q++) wS[q] = srcW[q];
    }

    for (int kc = 0; kc < Ktot; kc += 64) {
        { // regs -> smem (A transposed, scaled if nw)
            float rsc = nw ? rstd_s[lr] : 1.f;
#pragma unroll
            for (int q = 0; q < 4; q++) {
                float4 vv = aS[q];
                if (nw) {
                    float4 nv4 = *(const float4*)(nw + kc + lc + q * 4);
                    vv.x *= rsc * nv4.x; vv.y *= rsc * nv4.y;
                    vv.z *= rsc * nv4.z; vv.w *= rsc * nv4.w;
                }
                As[lc + q * 4 + 0][lr] = vv.x; As[lc + q * 4 + 1][lr] = vv.y;
                As[lc + q * 4 + 2][lr] = vv.z; As[lc + q * 4 + 3][lr] = vv.w;
            }
            if (wLayout == 0) {
#pragma unroll
                for (int q = 0; q < 4; q++) {
                    float4 vv = wS[q];
                    Ws[lc + q * 4 + 0][lr] = vv.x; Ws[lc + q * 4 + 1][lr] = vv.y;
                    Ws[lc + q * 4 + 2][lr] = vv.z; Ws[lc + q * 4 + 3][lr] = vv.w;
                }
            } else {
                float4* dst = (float4*)&Ws[lr][lc];
#pragma unroll
                for (int q = 0; q < 4; q++) dst[q] = wS[q];
            }
        }
        __syncthreads();
        // issue next chunk's global loads (latency hides behind compute)
        if (kc + 64 < Ktot) {
            const float4* srcA = (const float4*)(Ab + (size_t)lr * lda + kc + 64 + lc);
#pragma unroll
            for (int q = 0; q < 4; q++) aS[q] = srcA[q];
            const float4* srcW = (wLayout == 0)
                ? (const float4*)(Wb + (size_t)jrW * ldw + kc + 64 + lc)
                : (const float4*)(Wb + (size_t)(kc + 64 + lr) * ldw + jt * 64 + lc);
#pragma unroll
            for (int q = 0; q < 4; q++) wS[q] = srcW[q];
        }
#pragma unroll 16
        for (int kk = 0; kk < 64; kk++) {
            float4 a4 = *(const float4*)&As[kk][ty * 4];
            float4 w4 = *(const float4*)&Ws[kk][tx * 4];
            float2 w01 = make_float2(w4.x, w4.y), w23 = make_float2(w4.z, w4.w);
            fma2(acc[0][0], make_float2(a4.x, a4.x), w01);
            fma2(acc[0][1], make_float2(a4.x, a4.x), w23);
            fma2(acc[1][0], make_float2(a4.y, a4.y), w01);
            fma2(acc[1][1], make_float2(a4.y, a4.y), w23);
            fma2(acc[2][0], make_float2(a4.z, a4.z), w01);
            fma2(acc[2][1], make_float2(a4.z, a4.z), w23);
            fma2(acc[3][0], make_float2(a4.w, a4.w), w01);
            fma2(acc[3][1], make_float2(a4.w, a4.w), w23);
        }
        __syncthreads();
    }
    int b0 = ty * 4, j0 = tx * 4;
#pragma unroll
    for (int i = 0; i < 4; i++) {
        float vals[4] = {acc[i][0].x, acc[i][0].y, acc[i][1].x, acc[i][1].y};
#pragma unroll
        for (int u = 0; u < 4; u++) {
            int jg = jt * 64 + j0 + u;
            if (jg >= Nmax) continue;
            size_t ci = (size_t)(b0 + i) * ldc + jg;
            float vv = vals[u];
            if (mode == 0)      Cb[ci] = vv;
            else if (mode == 1) { vv += e1[jg]; Cb[ci] = 0.5f * vv * (1.f + erff(vv * 0.70710678118654752f)); }
            else if (mode == 3) { Cb[ci] = vv + e1[jg]; C2[ci] = vv + e2[jg]; }
            else if (mode == 4) Cb[ci] = vv * e1[jg];
            else if (mode == 5) Cb[ci] = vv + e1[jg];
            else if (mode == 6) Cb[ci] = vv + e2[ci];
        }
    }
}

// ---------------- rel-pos table ----------------
__global__ void k_rel() {
    int k = blockIdx.x, j = threadIdx.x;
    float p = (float)(1024 - k);
    int jj = (j < 256) ? j : j - 256;
    float invf = expf(-(float)jj * (9.210340371976184f / 256.0f));
    float a = p * invf;
    g_rel[k * Dz + j] = (j < 256) ? sinf(a) : cosf(a);
}

// ---------------- cat(stoch, action_norm) ----------------
__global__ __launch_bounds__(256) void k_prep(const float* __restrict__ stoch,
                                              const float* __restrict__ action) {
    int b = blockIdx.x, tid = threadIdx.x;
    for (int i = tid; i < 1024; i += 256) g_cat[b * SAz + i] = stoch[b * 1024 + i];
    if (tid < 64) {
        float a = action[b * 64 + tid];
        g_cat[b * SAz + 1024 + tid] = a / fmaxf(fabsf(a), 1.0f);
    }
}

// ---------------- silu(rmsnorm(tok)) -> g_x ----------------
__global__ __launch_bounds__(256) void k_silu(const float* __restrict__ inw) {
    int b = blockIdx.x, tid = threadIdx.x, w = tid >> 5, lane = tid & 31;
    __shared__ float red[9];
    float2 xv = ((const float2*)(g_tok + b * Dz))[tid];
    float ss = fmaf(xv.x, xv.x, xv.y * xv.y);
    ss = wred(ss);
    if (lane == 0) red[w] = ss;
    __syncthreads();
    if (tid == 0) { float t = 0; for (int i = 0; i < 8; i++) t += red[i]; red[8] = rsqrtf(t / 512.f + EPSRN); }
    __syncthreads();
    float rstd = red[8];
    float2 nv = ((const float2*)inw)[tid];
    float yx = xv.x * rstd * nv.x, yy = xv.y * rstd * nv.y;
    float2 o = make_float2(yx / (1.f + __expf(-yx)), yy / (1.f + __expf(-yy)));
    ((float2*)(g_x + b * Dz))[tid] = o;
}

// ---------------- streaming attention: 128 thr, 2 heads/warp, depth-4 ring ----------------
__global__ __launch_bounds__(128) void k_att(int l,
                                             const float* __restrict__ cache,
                                             float* __restrict__ ncache_l) {
    int c = blockIdx.x, b = blockIdx.y;
    int tid = threadIdx.x, w = tid >> 5, lane = tid & 31;
    __shared__ __align__(16) float rowb[DEPTH][Dz]; // 8KB ring
    const float* cache_l = cache + (size_t)l * Bz * Cz * Dz;
    int start = c * 32;
    int cnt = (c == NCH - 1) ? 33 : 32;
    int h0 = 2 * w;

    const float2* qa = (const float2*)(g_qkw + ((size_t)b * Hz + h0) * Dz);
    float2 qA[8], qB[8];
#pragma unroll
    for (int i = 0; i < 8; i++) { qA[i] = qa[lane + 32 * i]; qB[i] = qa[256 + lane + 32 * i]; }
    const float* bdA = g_bd + ((size_t)b * Hz + h0) * BDS;
    float mA = -1e30f, sA = 0.f, mB = -1e30f, sB = 0.f;
    float2 cA[8], cB[8];
#pragma unroll
    for (int i = 0; i < 8; i++) { cA[i] = make_float2(0.f, 0.f); cB[i] = make_float2(0.f, 0.f); }

    // prologue: 3 rows in flight
#pragma unroll
    for (int d = 0; d < 3; d++) {
        int k = start + d;
        if (d < cnt) {
            const float* src = (k < Cz) ? cache_l + ((size_t)b * Cz + k) * Dz
                                        : g_x + b * Dz;
            cpasync16(&rowb[d][tid * 4], src + tid * 4);
        }
        CP_COMMIT();
    }

    for (int r = 0; r < cnt; r++) {
        asm volatile("cp.async.wait_group 2;");
        __syncthreads();
        int kn = start + r + 3;
        if (r + 3 < cnt) {
            const float* src = (kn < Cz) ? cache_l + ((size_t)b * Cz + kn) * Dz
                                         : g_x + b * Dz;
            cpasync16(&rowb[(r + 3) & (DEPTH - 1)][tid * 4], src + tid * 4);
        }
        CP_COMMIT();
        int k = start + r;
        const float2* row2 = (const float2*)rowb[r & (DEPTH - 1)];
        float2 vA = make_float2(0.f, 0.f), vB = make_float2(0.f, 0.f), vS = make_float2(0.f, 0.f);
        float2 rr[8];
#pragma unroll
        for (int i = 0; i < 8; i++) {
            float2 rv = row2[lane + 32 * i];
            rr[i] = rv;
            fma2(vA, qA[i], rv);
            fma2(vB, qB[i], rv);
            fma2(vS, rv, rv);
        }
        float kA = vA.x + vA.y, kB = vB.x + vB.y, ssv = vS.x + vS.y;
#pragma unroll
        for (int o = 16; o; o >>= 1) {
            kA += __shfl_xor_sync(0xffffffffu, kA, o);
            kB += __shfl_xor_sync(0xffffffffu, kB, o);
            ssv += __shfl_xor_sync(0xffffffffu, ssv, o);
        }
        float rstd = rsqrtf(ssv * (1.f / 512.f) + EPSRN);
        float scA = ATT_SCALE * fmaf(rstd, kA, bdA[k]);
        float scB = ATT_SCALE * fmaf(rstd, kB, bdA[BDS + k]);
        float mnA = fmaxf(mA, scA);
        float pA = __expf(scA - mnA);
        if (mnA > mA && mA > -1e29f) {
            float al = __expf(mA - mnA);
            sA *= al;
#pragma unroll
            for (int i = 0; i < 8; i++) { cA[i].x *= al; cA[i].y *= al; }
        }
        mA = mnA; sA += pA;
        float mnB = fmaxf(mB, scB);
        float pB = __expf(scB - mnB);
        if (mnB > mB && mB > -1e29f) {
            float al = __expf(mB - mnB);
            sB *= al;
#pragma unroll
            for (int i = 0; i < 8; i++) { cB[i].x *= al; cB[i].y *= al; }
        }
        mB = mnB; sB += pB;
        float2 pA2 = make_float2(pA * rstd, pA * rstd);
        float2 pB2 = make_float2(pB * rstd, pB * rstd);
#pragma unroll
        for (int i = 0; i < 8; i++) { fma2(cA[i], pA2, rr[i]); fma2(cB[i], pB2, rr[i]); }
        if (k >= 1)
            __stcs(((float4*)(ncache_l + ((size_t)b * Cz + (k - 1)) * Dz)) + tid,
                   ((const float4*)row2)[tid]);
    }
    int pi = (b * NCH + c) * Hz + h0;
    if (lane == 0) { g_pm[pi] = mA; g_ps[pi] = sA; g_pm[pi + 1] = mB; g_ps[pi + 1] = sB; }
    float2* po = (float2*)(g_pctx + (size_t)pi * Dz);
#pragma unroll
    for (int i = 0; i < 8; i++) { po[lane + 32 * i] = cA[i]; po[256 + lane + 32 * i] = cB[i]; }
}

// ---------------- merge softmax partials + av GEMV (fused) ----------------
__global__ __launch_bounds__(256) void k_mav(int l, const float* __restrict__ n1w,
                                             const float* __restrict__ wv) {
    int b = blockIdx.x, h = blockIdx.y;
    int tid = threadIdx.x, w = tid >> 5, lane = tid & 31;
    __shared__ float wch[NCH];
    __shared__ float sinv;
    __shared__ __align__(16) float ctxs[Dz];
    if (tid < 32) {
        float mv = g_pm[(b * NCH + tid) * Hz + h];
        float M = mv;
#pragma unroll
        for (int o = 16; o; o >>= 1) M = fmaxf(M, __shfl_xor_sync(0xffffffffu, M, o));
        float e = __expf(mv - M);
        float sv = g_ps[(b * NCH + tid) * Hz + h] * e;
#pragma unroll
        for (int o = 16; o; o >>= 1) sv += __shfl_xor_sync(0xffffffffu, sv, o);
        wch[tid] = e;
        if (tid == 0) sinv = 1.f / sv;
    }
    __syncthreads();
    float2 acc = make_float2(0.f, 0.f);
#pragma unroll
    for (int ch = 0; ch < NCH; ch++) {
        float2 pv = ((const float2*)(g_pctx + (size_t)((b * NCH + ch) * Hz + h) * Dz))[tid];
        float2 w2 = make_float2(wch[ch], wch[ch]);
        fma2(acc, w2, pv);
    }
    float inv = sinv;
    float2 nv = ((const float2*)(n1w + l * Dz))[tid];
    acc.x *= inv * nv.x;
    acc.y *= inv * nv.y;
    ((float2*)ctxs)[tid] = acc;
    __syncthreads();
    const float* wvl = wv + ((size_t)l * Dz + (size_t)h * 64) * Dz;
    const float2* c2 = (const float2*)ctxs;
#pragma unroll
    for (int it = 0; it < 8; it++) {
        int j = w * 8 + it;
        const float2* wr2 = (const float2*)(wvl + (size_t)j * Dz);
        float2 a = make_float2(0.f, 0.f);
#pragma unroll
        for (int kq = 0; kq < 8; kq++) { int idx = lane + 32 * kq; fma2(a, c2[idx], wr2[idx]); }
        float rsum = wred(a.x + a.y);
        if (lane == 0) g_av[(size_t)b * Dz + h * 64 + j] = rsum;
    }
}

// ---------------- ff2 partial reduce + bias + residual -> new x (last layer) ----------------
__global__ __launch_bounds__(256) void k_ff2red(const float* __restrict__ b2l) {
    int b = blockIdx.x, tid = threadIdx.x;
    float2 s = ((const float2*)(g_part + (size_t)b * Dz))[tid];
#pragma unroll
    for (int ks = 1; ks < 4; ks++) {
        float2 p = ((const float2*)(g_part + (size_t)ks * Bz * Dz + (size_t)b * Dz))[tid];
        s.x += p.x; s.y += p.y;
    }
    float2 bb = ((const float2*)b2l)[tid];
    float2 hh = ((const float2*)(g_h + (size_t)b * Dz))[tid];
    ((float2*)(g_x + (size_t)b * Dz))[tid] = make_float2(s.x + bb.x + hh.x, s.y + bb.y + hh.y);
}

// ---------------- final ----------------
__global__ __launch_bounds__(256) void k_final(const float* __restrict__ summary,
                                               const float* __restrict__ onw,
                                               float* __restrict__ out_deter,
                                               float* __restrict__ out_summ) {
    int t = blockIdx.x, b = blockIdx.y, tid = threadIdx.x, w = tid >> 5, lane = tid & 31;
    __shared__ float row[Dz];
    __shared__ float red[9];
    const float* src = (t < Tz - 1) ? (summary + ((size_t)b * Tz + t + 1) * Dz) : (g_x + b * Dz);
    float ss = 0.f;
    for (int i = tid; i < Dz; i += 256) { float vv = src[i]; row[i] = vv; ss = fmaf(vv, vv, ss); }
    ss = wred(ss);
    if (lane == 0) red[w] = ss;
    __syncthreads();
    if (tid == 0) { float tt = 0; for (int i = 0; i < 8; i++) tt += red[i]; red[8] = rsqrtf(tt / 512.f + EPSRN); }
    __syncthreads();
    float rstd = red[8];
    for (int i = tid; i < Dz; i += 256) {
        out_summ[((size_t)b * Tz + t) * Dz + i] = row[i];
        out_deter[(size_t)b * (Tz * Dz) + t * Dz + i] = row[i] * rstd * onw[i];
    }
}

// ---------------- launch ----------------
extern "C" void kernel_launch(void* const* d_in, const int* in_sizes, int n_in,
                              void* d_out, int out_size) {
    (void)in_sizes; (void)n_in; (void)out_size;
    const float* stoch      = (const float*)d_in[0];
    const float* action     = (const float*)d_in[1];
    const float* cache      = (const float*)d_in[2];
    const float* summary    = (const float*)d_in[3];
    const float* in_w       = (const float*)d_in[4];
    const float* in_b       = (const float*)d_in[5];
    const float* in_norm_w  = (const float*)d_in[6];
    const float* n1w        = (const float*)d_in[7];
    const float* wq         = (const float*)d_in[8];
    const float* wk         = (const float*)d_in[9];
    const float* wv         = (const float*)d_in[10];
    const float* wr         = (const float*)d_in[11];
    const float* wo         = (const float*)d_in[12];
    const float* u          = (const float*)d_in[13];
    const float* v          = (const float*)d_in[14];
    const float* n2w        = (const float*)d_in[15];
    const float* ff_w1      = (const float*)d_in[16];
    const float* ff_b1      = (const float*)d_in[17];
    const float* ff_w2      = (const float*)d_in[18];
    const float* ff_b2      = (const float*)d_in[19];
    const float* out_norm_w = (const float*)d_in[20];

    float* out = (float*)d_out;
    float* out_deter = out;
    float* out_cache = out + (size_t)Bz * Tz * Dz;
    float* out_summ  = out_cache + (size_t)NL * Bz * Cz * Dz;

    float *p_cat, *p_tok, *p_x, *p_quk, *p_qur, *p_qkw, *p_rv, *p_bd,
          *p_rel, *p_av, *p_h, *p_ff, *p_part;
    cudaGetSymbolAddress((void**)&p_cat,  g_cat);
    cudaGetSymbolAddress((void**)&p_tok,  g_tok);
    cudaGetSymbolAddress((void**)&p_x,    g_x);
    cudaGetSymbolAddress((void**)&p_quk,  g_quk);
    cudaGetSymbolAddress((void**)&p_qur,  g_qur);
    cudaGetSymbolAddress((void**)&p_qkw,  g_qkw);
    cudaGetSymbolAddress((void**)&p_rv,   g_rv);
    cudaGetSymbolAddress((void**)&p_bd,   g_bd);
    cudaGetSymbolAddress((void**)&p_rel,  g_rel);
    cudaGetSymbolAddress((void**)&p_av,   g_av);
    cudaGetSymbolAddress((void**)&p_h,    g_h);
    cudaGetSymbolAddress((void**)&p_ff,   g_ff);
    cudaGetSymbolAddress((void**)&p_part, g_part);

    k_rel<<<LKV, 512>>>();
    k_prep<<<Bz, 256>>>(stoch, action);
    k_mm<<<8, 256>>>(p_cat, SAz, 0, 0, in_w, SAz, 0, 0, p_tok, Dz, 0,
                     SAz, Dz, 5, in_b, nullptr, nullptr, nullptr,
                     nullptr, nullptr, nullptr, 0,
                     nullptr, nullptr, nullptr, nullptr);
    k_silu<<<Bz, 256>>>(in_norm_w);

    for (int l = 0; l < NL; l++) {
        float* nc_l = out_cache + (size_t)l * Bz * Cz * Dz;
        const float* wql = wq + (size_t)l * Dz * Dz;
        const float* wkl = wk + (size_t)l * Dz * Dz;
        const float* wrl = wr + (size_t)l * Dz * Dz;
        const float* wol = wo + (size_t)l * Dz * Dz;

        // Q = rmsnorm(x)*n1 @ wq^T; for l>0 also materializes x from
        // prior layer's ff2 partials (fused ff2-reduce). Quk=Q+u, Qur=Q+v.
        k_mm<<<8, 256>>>(p_x, Dz, 0, 0, wql, Dz, 0, 0, p_quk, Dz, 0,
                         Dz, Dz, 3, u + l * Dz, v + l * Dz, p_qur, n1w + l * Dz,
                         nullptr, nullptr, nullptr, 0,
                         (l > 0) ? p_part : nullptr,
                         (l > 0) ? (ff_b2 + (size_t)(l - 1) * Dz) : nullptr,
                         p_h, p_x);
        // fused pair: z=0 qkw = Quk@wk_head * n1 ; z=1 rv = Qur@wr_head
        k_mm<<<dim3(8, 8, 2), 256>>>(p_quk, Dz, 0, 64, wkl, Dz, 64 * Dz, 1,
                                     p_qkw, Hz * Dz, Dz, 64, Dz, 4,
                                     n1w + l * Dz, nullptr, nullptr, nullptr,
                                     p_qur, wrl, p_rv, 0,
                                     nullptr, nullptr, nullptr, nullptr);
        // bd(512x1025) = rv @ rel^T
        k_mm<<<dim3(17, 8), 256>>>(p_rv, Dz, 0, 64 * Dz, p_rel, Dz, 0, 0,
                                   p_bd, BDS, 64 * BDS, Dz, LKV, 0,
                                   nullptr, nullptr, nullptr, nullptr,
                                   nullptr, nullptr, nullptr, 0,
                                   nullptr, nullptr, nullptr, nullptr);
        k_att<<<dim3(NCH, Bz), 128>>>(l, cache, nc_l);
        k_mav<<<dim3(Bz, Hz), 256>>>(l, n1w, wv);
        // h = x + av @ wo^T
        k_mm<<<8, 256>>>(p_av, Dz, 0, 0, wol, Dz, 0, 0, p_h, Dz, 0,
                         Dz, Dz, 6, nullptr, p_x, nullptr, nullptr,
                         nullptr, nullptr, nullptr, 0,
                         nullptr, nullptr, nullptr, nullptr);
        // ff hidden = gelu(rmsnorm(h)*n2 @ w1^T + b1)
        k_mm<<<32, 256>>>(p_h, Dz, 0, 0, ff_w1 + (size_t)l * FFz * Dz, Dz, 0, 0,
                          p_ff, FFz, 0, Dz, FFz, 1,
                          ff_b1 + (size_t)l * FFz, nullptr, nullptr, n2w + l * Dz,
                          nullptr, nullptr, nullptr, 0,
                          nullptr, nullptr, nullptr, nullptr);
        // ff2 split-K partials (reduced by next layer's Q k_mm, or k_ff2red at end)
        k_mm<<<dim3(8, 4), 256>>>(p_ff, FFz, 0, 512, ff_w2 + (size_t)l * Dz * FFz, FFz, 512, 0,
                                  p_part, Dz, Bz * Dz, 512, Dz, 0,
                                  nullptr, nullptr, nullptr, nullptr,
                                  nullptr, nullptr, nullptr, 0,
                                  nullptr, nullptr, nullptr, nullptr);
    }
    k_ff2red<<<Bz, 256>>>(ff_b2 + (size_t)(NL - 1) * Dz);
    k_final<<<dim3(Tz, Bz), 256>>>(summary, out_norm_w, out_deter, out_summ);
}